// round 17
// baseline (speedup 1.0000x reference)
#include <cuda_runtime.h>
#include <cuda_fp16.h>
#include <cstdint>
#include <math.h>

#define TOKENS 8192
#define DMODEL 1024
#define DFF    4096
#define RANK   128
#define MT     64

// ---- smem word map (per CTA; 2 CTAs/SM) ----
#define W_MB 0             // 2 mbarriers (8B each), padded to 16 words
#define W_SA 16            // t1/t2: 64 x 80 (padded, pw) = 5120
#define W_SH 5136          // h:     64 x 48 (padded, pw) = 3072
#define W_B  8208          // 2 staging buffers (dense, swizzled)
#define BSZ  8192          // per buffer: slotA 4096 w + slotB 4096 w
#define SLOTB 4096
#define SMEM_WORDS 24592   // 98368 B -> 2 CTAs/SM
#define S80 80
#define S48 48

// ---- chunk-contiguous fp16 scratch (prep outputs; dense + pw + unit-swizzle) ----
__device__ uint32_t g_xh[128 * 16 * 64 * 32]; // [tile][chunk][row64][word32]
__device__ uint32_t g_v1[64 * 64 * 64];       // [it][f-row][word]   (K=128 -> 64 w)
__device__ uint32_t g_u2[64 * 128 * 32];      // [it][r-row][word]   (K=64  -> 32 w)
__device__ uint32_t g_u1[16 * 128 * 32];      // [ci][r-row][word]
__device__ uint32_t g_v2[16 * 64 * 64];       // [dc][d-row][word]

__device__ __forceinline__ int pw(int w) {    // permute low 4 bits (self-inverse)
    return (w & ~15) | ((w & 3) << 2) | ((w >> 2) & 3);
}
__device__ __forceinline__ uint32_t pk(float lo, float hi) {
    __half2 h = __floats2half2_rn(lo, hi);
    return *(uint32_t*)&h;
}
__device__ __forceinline__ float gelu_exact(float v) {
    return 0.5f * v * (1.f + erff(v * 0.7071067811865476f));
}
__device__ __forceinline__ void mma16(float* c,
                                      uint32_t a0, uint32_t a1, uint32_t a2, uint32_t a3,
                                      uint32_t b0, uint32_t b1) {
    asm volatile(
        "mma.sync.aligned.m16n8k16.row.col.f32.f16.f16.f32 "
        "{%0,%1,%2,%3}, {%4,%5,%6,%7}, {%8,%9}, {%0,%1,%2,%3};\n"
        : "+f"(c[0]), "+f"(c[1]), "+f"(c[2]), "+f"(c[3])
        : "r"(a0), "r"(a1), "r"(a2), "r"(a3), "r"(b0), "r"(b1));
}

#define BAR_RG(rg) asm volatile("bar.sync %0, 128;\n" :: "r"(1 + (rg)) : "memory")
#define MBAR_INIT(m, c) asm volatile("mbarrier.init.shared.b64 [%0], %1;" :: "r"(m), "r"(c) : "memory")
#define MBAR_EXPECT(m, bytes) asm volatile("mbarrier.arrive.expect_tx.shared.b64 _, [%0], %1;" :: "r"(m), "r"(bytes) : "memory")
#define TMA1D(dst, src, bytes, bar) \
    asm volatile("cp.async.bulk.shared::cluster.global.mbarrier::complete_tx::bytes [%0], [%1], %2, [%3];" \
        :: "r"(dst), "l"(src), "r"(bytes), "r"(bar) : "memory")

#define MBAR_WAIT(mb, par) do {                                            \
    uint32_t _m = (mb), _p = (par), _d;                                    \
    asm volatile("{\n\t.reg .pred p;\n\t"                                  \
        "mbarrier.try_wait.parity.acquire.cta.shared::cta.b64 p, [%1], %2;\n\t" \
        "selp.b32 %0, 1, 0, p;\n\t}" : "=r"(_d) : "r"(_m), "r"(_p) : "memory"); \
    if (!_d) {                                                             \
        asm volatile("{\n\t.reg .pred P1;\n\t"                             \
            "WL_%=:\n\t"                                                   \
            "mbarrier.try_wait.parity.acquire.cta.shared::cta.b64 P1, [%0], %1, 0x989680;\n\t" \
            "@P1 bra.uni WD_%=;\n\t"                                       \
            "bra.uni WL_%=;\n\t"                                           \
            "WD_%=:\n\t}" :: "r"(_m), "r"(_p) : "memory");                 \
    }                                                                      \
} while (0)

// Warp GEMM: 32 A-rows at mrow, NT n-tiles of 8, K = KG*32.
// AD: A dense+swizzled (AW words/row) vs padded (stride AW, pw offsets).
// B always dense+swizzled (BW words/row). One LDS.128 feeds two k16 steps.
template<int NT, int KG, bool AD, int AW, int BW>
__device__ __forceinline__ void gemmx(const uint32_t* __restrict__ A,
                                      const uint32_t* __restrict__ B,
                                      int mrow, int ncol, int qr, int qc, float (*acc)[4])
{
    #pragma unroll
    for (int kg = 0; kg < KG; kg++) {
        const int su = ((kg * 4 + qc) ^ qr) << 2;    // dense: rows ≡ qr (mod 8)
        const int ao = AD ? su : (kg * 16 + qc * 4);
        uint4 a0 = *(const uint4*)(A + (mrow + qr)      * AW + ao);
        uint4 a1 = *(const uint4*)(A + (mrow + qr + 8)  * AW + ao);
        uint4 a2 = *(const uint4*)(A + (mrow + qr + 16) * AW + ao);
        uint4 a3 = *(const uint4*)(A + (mrow + qr + 24) * AW + ao);
        uint4 b[NT];
        #pragma unroll
        for (int nt = 0; nt < NT; nt++)
            b[nt] = *(const uint4*)(B + (ncol + nt * 8 + qr) * BW + su);
        #pragma unroll
        for (int nt = 0; nt < NT; nt++) {
            mma16(acc[nt],      a0.x, a1.x, a0.y, a1.y, b[nt].x, b[nt].y);
            mma16(acc[nt],      a0.z, a1.z, a0.w, a1.w, b[nt].z, b[nt].w);
            mma16(acc[NT + nt], a2.x, a3.x, a2.y, a3.y, b[nt].x, b[nt].y);
            mma16(acc[NT + nt], a2.z, a3.z, a2.w, a3.w, b[nt].z, b[nt].w);
        }
    }
}

// ---------------- prep: x -> fp16 tiled/permuted/swizzled (2 words/thread ILP) ----------------
__global__ void prep_x_kernel(const float* __restrict__ x) {
    int base = (blockIdx.x * 256 + threadIdx.x) * 2;      // 4,194,304 words total
    #pragma unroll
    for (int k = 0; k < 2; k++) {
        int idx = base + k;
        int phys = idx & 31, row = (idx >> 5) & 63;
        int chunk = (idx >> 11) & 15, tile = idx >> 15;
        int p = (((phys >> 2) ^ (row & 7)) << 2) | (phys & 3);
        int w = pw(p);
        int tok = tile * 64 + row;
        int d0 = chunk * 64 + 2 * w;
        g_xh[idx] = pk(x[(size_t)tok * DMODEL + d0], x[(size_t)tok * DMODEL + d0 + 1]);
    }
}

// ---------------- prep: weights (fold S, transpose, permute, swizzle) ----------------
__global__ void prep_w_kernel(const float* __restrict__ cfc_U, const float* __restrict__ cfc_S,
                              const float* __restrict__ cfc_V,
                              const float* __restrict__ cp_U,  const float* __restrict__ cp_S,
                              const float* __restrict__ cp_V) {
    int b = blockIdx.x, t = threadIdx.x;
    if (b < 1024) {                                  // g_v1 [it][f-row 64][w 64]
        int o = b * 256 + t;
        int phys = o & 63, row = (o >> 6) & 63, it = o >> 12;
        int p = (((phys >> 2) ^ (row & 7)) << 2) | (phys & 3);
        int w = pw(p);
        int f = it * 64 + row;
        g_v1[o] = pk(cfc_V[(size_t)f * RANK + 2 * w], cfc_V[(size_t)f * RANK + 2 * w + 1]);
    } else if (b < 2048) {                           // g_u2 [it][r 128][w 32]
        int o = (b - 1024) * 256 + t;
        int phys = o & 31, r = (o >> 5) & 127, it = o >> 12;
        int p = (((phys >> 2) ^ (r & 7)) << 2) | (phys & 3);
        int w = pw(p);
        int f0 = it * 64 + 2 * w;
        float s = cp_S[r];
        g_u2[o] = pk(cp_U[(size_t)f0 * RANK + r] * s, cp_U[(size_t)(f0 + 1) * RANK + r] * s);
    } else if (b < 2304) {                           // g_u1 [ci][r 128][w 32]
        int o = (b - 2048) * 256 + t;
        int phys = o & 31, r = (o >> 5) & 127, ci = o >> 12;
        int p = (((phys >> 2) ^ (r & 7)) << 2) | (phys & 3);
        int w = pw(p);
        int d0 = ci * 64 + 2 * w;
        float s = cfc_S[r];
        g_u1[o] = pk(cfc_U[(size_t)d0 * RANK + r] * s, cfc_U[(size_t)(d0 + 1) * RANK + r] * s);
    } else {                                         // g_v2 [dc][d-row 64][w 64]
        int o = (b - 2304) * 256 + t;
        int phys = o & 63, row = (o >> 6) & 63, dc = o >> 12;
        int p = (((phys >> 2) ^ (row & 7)) << 2) | (phys & 3);
        int w = pw(p);
        int d = dc * 64 + row;
        g_v2[o] = pk(cp_V[(size_t)d * RANK + 2 * w], cp_V[(size_t)d * RANK + 2 * w + 1]);
    }
}

// ---------------- main fused kernel: TMA-staged, 2 CTAs/SM ----------------
__global__ void __launch_bounds__(256, 2)
fused_lowrank_mlp_kernel(const float* __restrict__ cfc_b,
                         const float* __restrict__ cp_b,
                         float* __restrict__ out)
{
    extern __shared__ uint32_t sm[];
    const uint32_t smb = (uint32_t)__cvta_generic_to_shared(sm);
    uint32_t* SA = sm + W_SA;
    uint32_t* SH = sm + W_SH;

    const int tid  = threadIdx.x;
    const int lane = tid & 31;
    const int warp = tid >> 5;
    const int qr   = lane >> 2;
    const int qc   = lane & 3;
    const int rg   = warp >> 2;          // 2 row groups of 32
    const int cg   = warp & 3;           // 4 col groups
    const int mrow = rg * 32;
    const int m0   = blockIdx.x * MT;

    auto mb   = [&](int i) { return smb + W_MB * 4u + i * 8u; };
    auto bufp = [&](int g) { return sm + W_B + (g & 1) * BSZ; };
    auto bufa = [&](int g) { return smb + (W_B + (g & 1) * BSZ) * 4u; };

    if (tid == 0) { MBAR_INIT(mb(0), 1); MBAR_INIT(mb(1), 1); }
    __syncthreads();

    // unified producer: stage global chunk g (tid 0 only).
    // g 0..15: phase1 (x + U1); 16..79: phase2 (V1 + U2); 80..95: phase3 (V2)
    auto stage_chunk = [&](int g) {
        uint32_t d = bufa(g), bar = mb(g & 1);
        if (g < 16) {
            MBAR_EXPECT(bar, 24576u);
            TMA1D(d, g_xh + ((size_t)blockIdx.x * 16 + g) * 2048, 8192u, bar);
            TMA1D(d + SLOTB * 4u, g_u1 + (size_t)g * 4096, 16384u, bar);
        } else if (g < 80) {
            int c = g - 16;
            MBAR_EXPECT(bar, 32768u);
            TMA1D(d, g_v1 + (size_t)c * 4096, 16384u, bar);
            TMA1D(d + SLOTB * 4u, g_u2 + (size_t)c * 4096, 16384u, bar);
        } else {
            int c = g - 80;
            MBAR_EXPECT(bar, 16384u);
            TMA1D(d, g_v2 + (size_t)c * 4096, 16384u, bar);
        }
    };

    int gc = 0;                                      // consumer chunk counter
    auto wait_chunk = [&]() {
        MBAR_WAIT(mb(gc & 1), (uint32_t)((gc >> 1) & 1));
        gc++;
    };

    if (tid == 0) { stage_chunk(0); stage_chunk(1); }

    // ================= Phase 1: t1[64x128] = x @ (U1*S) =================
    float acc1[8][4];
    #pragma unroll
    for (int i = 0; i < 8; i++)
        #pragma unroll
        for (int j = 0; j < 4; j++) acc1[i][j] = 0.f;

    for (int ci = 0; ci < 16; ci++) {
        wait_chunk();
        __syncthreads();
        const uint32_t* bp = bufp(ci);
        gemmx<4, 2, true, 32, 32>(bp, bp + SLOTB, mrow, cg * 32, qr, qc, acc1);
        __syncthreads();                             // buffer ci&1 free
        if (tid == 0 && ci + 2 < 96) stage_chunk(ci + 2);
    }

    // t1 epilogue -> SA (padded, pw)
    #pragma unroll
    for (int nt = 0; nt < 4; nt++) {
        int p = pw(cg * 16 + nt * 4 + qc);
        SA[(mrow + qr) * S80 + p]      = pk(acc1[nt][0], acc1[nt][1]);
        SA[(mrow + qr + 8) * S80 + p]  = pk(acc1[nt][2], acc1[nt][3]);
        SA[(mrow + qr + 16) * S80 + p] = pk(acc1[4 + nt][0], acc1[4 + nt][1]);
        SA[(mrow + qr + 24) * S80 + p] = pk(acc1[4 + nt][2], acc1[4 + nt][3]);
    }

    // ===== Phase 2: 64 f-chunks; t2[64x128] in registers =====
    float t2a[8][4];
    #pragma unroll
    for (int i = 0; i < 8; i++)
        #pragma unroll
        for (int j = 0; j < 4; j++) t2a[i][j] = 0.f;

    for (int it = 0; it < 64; it++) {
        wait_chunk();
        __syncthreads();                             // also orders SA writes (it==0)
        const uint32_t* bp = bufp(16 + it);

        // GEMM2: h[64x64] = t1 @ V1c^T (K=128); warp tile 32x16
        float ha[4][4];
        #pragma unroll
        for (int i = 0; i < 4; i++)
            #pragma unroll
            for (int j = 0; j < 4; j++) ha[i][j] = 0.f;
        gemmx<2, 4, false, S80, 64>(SA, bp, mrow, cg * 16, qr, qc, ha);

        // bias + exact GELU -> SH (padded, pw)
        #pragma unroll
        for (int nt = 0; nt < 2; nt++) {
            int c0 = cg * 16 + nt * 8 + 2 * qc;
            int fb = it * 64 + c0;
            float b0 = __ldg(cfc_b + fb), b1 = __ldg(cfc_b + fb + 1);
            int p = pw(cg * 8 + nt * 4 + qc);
            SH[(mrow + qr) * S48 + p] =
                pk(gelu_exact(ha[nt][0] + b0), gelu_exact(ha[nt][1] + b1));
            SH[(mrow + qr + 8) * S48 + p] =
                pk(gelu_exact(ha[nt][2] + b0), gelu_exact(ha[nt][3] + b1));
            SH[(mrow + qr + 16) * S48 + p] =
                pk(gelu_exact(ha[2 + nt][0] + b0), gelu_exact(ha[2 + nt][1] + b1));
            SH[(mrow + qr + 24) * S48 + p] =
                pk(gelu_exact(ha[2 + nt][2] + b0), gelu_exact(ha[2 + nt][3] + b1));
        }
        BAR_RG(rg);

        // GEMM3: t2 += h @ (U2*S2)c (K=64); warp tile 32x32
        gemmx<4, 2, false, S48, 32>(SH, bp + SLOTB, mrow, cg * 32, qr, qc, t2a);
        __syncthreads();                             // buffer (16+it)&1 free
        if (tid == 0 && 16 + it + 2 < 96) stage_chunk(16 + it + 2);
    }

    // t2 epilogue -> SA (reuse; last sync covers all GEMM2 reads of SA)
    #pragma unroll
    for (int nt = 0; nt < 4; nt++) {
        int p = pw(cg * 16 + nt * 4 + qc);
        SA[(mrow + qr) * S80 + p]      = pk(t2a[nt][0], t2a[nt][1]);
        SA[(mrow + qr + 8) * S80 + p]  = pk(t2a[nt][2], t2a[nt][3]);
        SA[(mrow + qr + 16) * S80 + p] = pk(t2a[4 + nt][0], t2a[4 + nt][1]);
        SA[(mrow + qr + 24) * S80 + p] = pk(t2a[4 + nt][2], t2a[4 + nt][3]);
    }

    // ================= Phase 3: out = t2 @ V2^T + b2 =================
    for (int dc = 0; dc < 16; dc++) {
        wait_chunk();
        __syncthreads();                             // orders SA writes (dc==0)

        float oa[4][4];
        #pragma unroll
        for (int i = 0; i < 4; i++)
            #pragma unroll
            for (int j = 0; j < 4; j++) oa[i][j] = 0.f;
        gemmx<2, 4, false, S80, 64>(SA, bufp(80 + dc), mrow, cg * 16, qr, qc, oa);

        #pragma unroll
        for (int nt = 0; nt < 2; nt++) {
            int c0 = cg * 16 + nt * 8 + 2 * qc;
            int db = dc * 64 + c0;
            float b0 = __ldg(cp_b + db), b1 = __ldg(cp_b + db + 1);
            int r0 = m0 + mrow + qr;
            *(float2*)(out + (size_t)r0 * DMODEL + db) =
                make_float2(oa[nt][0] + b0, oa[nt][1] + b1);
            *(float2*)(out + (size_t)(r0 + 8) * DMODEL + db) =
                make_float2(oa[nt][2] + b0, oa[nt][3] + b1);
            *(float2*)(out + (size_t)(r0 + 16) * DMODEL + db) =
                make_float2(oa[2 + nt][0] + b0, oa[2 + nt][1] + b1);
            *(float2*)(out + (size_t)(r0 + 24) * DMODEL + db) =
                make_float2(oa[2 + nt][2] + b0, oa[2 + nt][3] + b1);
        }
        __syncthreads();                             // buffer (80+dc)&1 free
        if (tid == 0 && 80 + dc + 2 < 96) stage_chunk(80 + dc + 2);
    }
}

extern "C" void kernel_launch(void* const* d_in, const int* in_sizes, int n_in,
                              void* d_out, int out_size)
{
    const float* x     = (const float*)d_in[0];
    const float* cfc_U = (const float*)d_in[1];
    const float* cfc_S = (const float*)d_in[2];
    const float* cfc_V = (const float*)d_in[3];
    const float* cfc_b = (const float*)d_in[4];
    const float* cp_U  = (const float*)d_in[5];
    const float* cp_S  = (const float*)d_in[6];
    const float* cp_V  = (const float*)d_in[7];
    const float* cp_b  = (const float*)d_in[8];
    float* out = (float*)d_out;

    prep_x_kernel<<<8192, 256>>>(x);
    prep_w_kernel<<<2560, 256>>>(cfc_U, cfc_S, cfc_V, cp_U, cp_S, cp_V);

    const int smem_bytes = SMEM_WORDS * 4;   // 98368 -> 2 CTAs/SM
    cudaFuncSetAttribute(fused_lowrank_mlp_kernel,
                         cudaFuncAttributeMaxDynamicSharedMemorySize, smem_bytes);
    fused_lowrank_mlp_kernel<<<TOKENS / MT, 256, smem_bytes>>>(cfc_b, cp_b, out);
}